// round 14
// baseline (speedup 1.0000x reference)
#include <cuda_runtime.h>

#define NROWS 16384
#define DCOLS 2048
#define TPB   256
#define RPB   4                          // 4 consecutive rows per CTA, 2 warps/row
#define GRID  (NROWS / RPB)              // 4096 CTAs, last one also reduces

// Device-global scratch (no allocations allowed).
__device__ float        g_partial[GRID];
__device__ unsigned int g_counter = 0;   // last CTA resets -> replay-safe

__device__ __forceinline__ unsigned int atom_acq_rel_add(unsigned int* p, unsigned int v) {
    unsigned int old;
    asm volatile("atom.acq_rel.gpu.global.add.u32 %0, [%1], %2;"
                 : "=r"(old) : "l"(p), "r"(v) : "memory");
    return old;
}

__global__ void __launch_bounds__(TPB, 8) cosine_loss_kernel(
    const float* __restrict__ cxr, const float* __restrict__ ehr,
    float* __restrict__ out)
{
    const int t    = threadIdx.x;
    const int lane = t & 31;
    const int warp = t >> 5;
    __shared__ float sdot[8], sna[8], snb[8];
    __shared__ bool  s_is_last;

    // ── Worker: 4 consecutive rows; warp w covers half (w&1) of row (w>>1).
    // 32 KB contiguous per tensor per CTA (best-measured mainloop).
    {
        const int row_in_blk = warp >> 1;        // 0..3
        const int half       = warp & 1;         // 0..1
        const size_t off = ((size_t)blockIdx.x * RPB + row_in_blk) * (DCOLS / 4)
                         + half * 256 + lane;
        const float4* __restrict__ a = reinterpret_cast<const float4*>(ehr) + off;
        const float4* __restrict__ b = reinterpret_cast<const float4*>(cxr) + off;

        float dot = 0.f, na = 0.f, nb = 0.f;

        // 256 float4 per tensor per warp -> 8 per lane; 4 chunks of MLP=4.
        // A/B vs R13: plain cached loads instead of __ldcs.
        #pragma unroll
        for (int c = 0; c < 4; c++) {
            float4 a0 = a[64 * c];
            float4 b0 = b[64 * c];
            float4 a1 = a[64 * c + 32];
            float4 b1 = b[64 * c + 32];

            dot += a0.x*b0.x + a0.y*b0.y + a0.z*b0.z + a0.w*b0.w;
            na  += a0.x*a0.x + a0.y*a0.y + a0.z*a0.z + a0.w*a0.w;
            nb  += b0.x*b0.x + b0.y*b0.y + b0.z*b0.z + b0.w*b0.w;

            dot += a1.x*b1.x + a1.y*b1.y + a1.z*b1.z + a1.w*b1.w;
            na  += a1.x*a1.x + a1.y*a1.y + a1.z*a1.z + a1.w*a1.w;
            nb  += b1.x*b1.x + b1.y*b1.y + b1.z*b1.z + b1.w*b1.w;
        }

        #pragma unroll
        for (int o = 16; o > 0; o >>= 1) {
            dot += __shfl_xor_sync(0xffffffffu, dot, o);
            na  += __shfl_xor_sync(0xffffffffu, na,  o);
            nb  += __shfl_xor_sync(0xffffffffu, nb,  o);
        }

        if (lane == 0) { sdot[warp] = dot; sna[warp] = na; snb[warp] = nb; }
        __syncthreads();

        if (t == 0) {
            float csum = 0.f;
            #pragma unroll
            for (int r = 0; r < RPB; r++) {
                float d = sdot[2*r] + sdot[2*r + 1];
                float x = sna [2*r] + sna [2*r + 1];
                float y = snb [2*r] + snb [2*r + 1];
                csum += d * rsqrtf(x * y);
            }
            g_partial[blockIdx.x] = csum;
            // acq_rel: releases the partial store, acquires others' partials.
            unsigned int old = atom_acq_rel_add(&g_counter, 1u);
            s_is_last = (old == (unsigned)(GRID - 1));
        }
        __syncthreads();
    }

    if (!s_is_last) return;

    // ── Last CTA (already hot): reduce 4096 partials (16 KB, L2-resident) ──
    const float4* rp = reinterpret_cast<const float4*>(g_partial);
    float4 v0 = __ldcg(&rp[t]);
    float4 v1 = __ldcg(&rp[t +     TPB]);
    float4 v2 = __ldcg(&rp[t + 2 * TPB]);
    float4 v3 = __ldcg(&rp[t + 3 * TPB]);
    float s = v0.x + v0.y + v0.z + v0.w
            + v1.x + v1.y + v1.z + v1.w
            + v2.x + v2.y + v2.z + v2.w
            + v3.x + v3.y + v3.z + v3.w;

    #pragma unroll
    for (int o = 16; o > 0; o >>= 1)
        s += __shfl_xor_sync(0xffffffffu, s, o);

    if (lane == 0) sdot[warp] = s;
    __syncthreads();

    if (t == 0) {
        float tot = 0.f;
        #pragma unroll
        for (int i = 0; i < 8; i++) tot += sdot[i];
        out[0] = 1.0f - tot / (float)NROWS;
        __threadfence();
        g_counter = 0;                            // reset for next graph replay
    }
}

extern "C" void kernel_launch(void* const* d_in, const int* in_sizes, int n_in,
                              void* d_out, int out_size)
{
    const float* cxr = (const float*)d_in[0];
    const float* ehr = (const float*)d_in[1];
    float* out = (float*)d_out;
    cosine_loss_kernel<<<GRID, TPB>>>(cxr, ehr, out);
}

// round 15
// speedup vs baseline: 1.0383x; 1.0383x over previous
#include <cuda_runtime.h>

#define NROWS 16384
#define DCOLS 2048
#define TPB   256
#define RPB   4                          // 4 consecutive rows per CTA, 2 warps/row
#define GRID  (NROWS / RPB)              // 4096 CTAs, last one also reduces

// Device-global scratch (no allocations allowed).
__device__ float        g_partial[GRID];
__device__ unsigned int g_counter = 0;   // last CTA resets -> replay-safe

__device__ __forceinline__ unsigned int atom_acq_rel_add(unsigned int* p, unsigned int v) {
    unsigned int old;
    asm volatile("atom.acq_rel.gpu.global.add.u32 %0, [%1], %2;"
                 : "=r"(old) : "l"(p), "r"(v) : "memory");
    return old;
}

__global__ void __launch_bounds__(TPB, 8) cosine_loss_kernel(
    const float* __restrict__ cxr, const float* __restrict__ ehr,
    float* __restrict__ out)
{
    const int t    = threadIdx.x;
    const int lane = t & 31;
    const int warp = t >> 5;
    __shared__ float sdot[8], sna[8], snb[8];
    __shared__ bool  s_is_last;

    // ── Worker: 4 consecutive rows; warp w covers half (w&1) of row (w>>1).
    // 32 KB contiguous per tensor per CTA (best-measured mainloop).
    {
        const int row_in_blk = warp >> 1;        // 0..3
        const int half       = warp & 1;         // 0..1
        const size_t off = ((size_t)blockIdx.x * RPB + row_in_blk) * (DCOLS / 4)
                         + half * 256 + lane;
        const float4* a = reinterpret_cast<const float4*>(ehr) + off;
        const float4* b = reinterpret_cast<const float4*>(cxr) + off;

        float dot = 0.f, na = 0.f, nb = 0.f;

        // 256 float4 per tensor per warp -> 8 per lane; 4 chunks of MLP=4.
        // __ldcs (evict-first) A/B-verified: +3.7% BW on this dual stream.
        #pragma unroll
        for (int c = 0; c < 4; c++) {
            float4 a0 = __ldcs(a + 64 * c);
            float4 b0 = __ldcs(b + 64 * c);
            float4 a1 = __ldcs(a + 64 * c + 32);
            float4 b1 = __ldcs(b + 64 * c + 32);

            dot += a0.x*b0.x + a0.y*b0.y + a0.z*b0.z + a0.w*b0.w;
            na  += a0.x*a0.x + a0.y*a0.y + a0.z*a0.z + a0.w*a0.w;
            nb  += b0.x*b0.x + b0.y*b0.y + b0.z*b0.z + b0.w*b0.w;

            dot += a1.x*b1.x + a1.y*b1.y + a1.z*b1.z + a1.w*b1.w;
            na  += a1.x*a1.x + a1.y*a1.y + a1.z*a1.z + a1.w*a1.w;
            nb  += b1.x*b1.x + b1.y*b1.y + b1.z*b1.z + b1.w*b1.w;
        }

        #pragma unroll
        for (int o = 16; o > 0; o >>= 1) {
            dot += __shfl_xor_sync(0xffffffffu, dot, o);
            na  += __shfl_xor_sync(0xffffffffu, na,  o);
            nb  += __shfl_xor_sync(0xffffffffu, nb,  o);
        }

        if (lane == 0) { sdot[warp] = dot; sna[warp] = na; snb[warp] = nb; }
        __syncthreads();

        if (t == 0) {
            float csum = 0.f;
            #pragma unroll
            for (int r = 0; r < RPB; r++) {
                float d = sdot[2*r] + sdot[2*r + 1];
                float x = sna [2*r] + sna [2*r + 1];
                float y = snb [2*r] + snb [2*r + 1];
                csum += d * rsqrtf(x * y);
            }
            g_partial[blockIdx.x] = csum;
            // acq_rel: releases the partial store, acquires others' partials.
            unsigned int old = atom_acq_rel_add(&g_counter, 1u);
            s_is_last = (old == (unsigned)(GRID - 1));
        }
        __syncthreads();
    }

    if (!s_is_last) return;

    // ── Last CTA (already hot): reduce 4096 partials (16 KB, L2-resident) ──
    const float4* rp = reinterpret_cast<const float4*>(g_partial);
    float4 v0 = __ldcg(&rp[t]);
    float4 v1 = __ldcg(&rp[t +     TPB]);
    float4 v2 = __ldcg(&rp[t + 2 * TPB]);
    float4 v3 = __ldcg(&rp[t + 3 * TPB]);
    float s = v0.x + v0.y + v0.z + v0.w
            + v1.x + v1.y + v1.z + v1.w
            + v2.x + v2.y + v2.z + v2.w
            + v3.x + v3.y + v3.z + v3.w;

    #pragma unroll
    for (int o = 16; o > 0; o >>= 1)
        s += __shfl_xor_sync(0xffffffffu, s, o);

    if (lane == 0) sdot[warp] = s;
    __syncthreads();

    if (t == 0) {
        float tot = 0.f;
        #pragma unroll
        for (int i = 0; i < 8; i++) tot += sdot[i];
        out[0] = 1.0f - tot / (float)NROWS;
        __threadfence();
        g_counter = 0;                            // reset for next graph replay
    }
}

extern "C" void kernel_launch(void* const* d_in, const int* in_sizes, int n_in,
                              void* d_out, int out_size)
{
    const float* cxr = (const float*)d_in[0];
    const float* ehr = (const float*)d_in[1];
    float* out = (float*)d_out;
    cosine_loss_kernel<<<GRID, TPB>>>(cxr, ehr, out);
}